// round 13
// baseline (speedup 1.0000x reference)
#include <cuda_runtime.h>
#include <cuda_bf16.h>

// RobustSum L1 IRLS (K=3): x(128,1024) @ W(1024,1024) -> z(128,1024), fp32.
//
// Per (b,o): c = z/D1; t_i = x_i*W_io - c; r_i = 1/(|t_i|+eps);
// q = sum r_i t_i, sw = sum r_i; c' = (q + c*sw)/max(sw,1e-12); out = D1*c.
// Pairing (exact): with d = |t|+eps,
//   r_i + r_j       = (d_i+d_j) * rcp(d_i*d_j)
//   r_i t_i+r_j t_j = (t_i d_j + t_j d_i) * rcp(d_i*d_j)
//
// R13 = R12 (winner, 145us) + pre-duplicated x in smem: xsd[i] holds
// {(x_b0,x_b0),(x_b1,x_b1)} so one LDS.128 feeds fma2 directly — kills the
// 4 pack2(x,x) movs per 2i-step (and 2 per pass-0 step) that made alu the
// co-binding pipe (43.8%). instr/lane-el ~4.6 -> ~4.1.
// Shape unchanged: thread = 2b x 2o, paired i; block = 128 thr = 4 warps
// (warp = 256-i chunk); block = 2b x 64o; grid (16,64) = 1024 blocks.

#define DIN     1024
#define DOUT    1024
#define KITER   3
#define EPSILON 0.001f
#define ICHUNK  256
#define NTHREADS 128

typedef unsigned long long ull;

__device__ __forceinline__ ull pack2(float lo, float hi) {
    ull r; asm("mov.b64 %0, {%1,%2};" : "=l"(r) : "f"(lo), "f"(hi)); return r;
}
__device__ __forceinline__ void unpack2(ull v, float& lo, float& hi) {
    asm("mov.b64 {%0,%1}, %2;" : "=f"(lo), "=f"(hi) : "l"(v));
}
__device__ __forceinline__ ull fma2(ull a, ull b, ull c) {
    ull r; asm("fma.rn.f32x2 %0, %1, %2, %3;" : "=l"(r) : "l"(a), "l"(b), "l"(c)); return r;
}
__device__ __forceinline__ ull add2(ull a, ull b) {
    ull r; asm("add.rn.f32x2 %0, %1, %2;" : "=l"(r) : "l"(a), "l"(b)); return r;
}
__device__ __forceinline__ ull mul2(ull a, ull b) {
    ull r; asm("mul.rn.f32x2 %0, %1, %2;" : "=l"(r) : "l"(a), "l"(b)); return r;
}
__device__ __forceinline__ float rcpf(float a) {
    float r; asm("rcp.approx.f32 %0, %1;" : "=f"(r) : "f"(a)); return r;
}
__device__ __forceinline__ ull rcp2(ull m) {
    float a, b; unpack2(m, a, b);
    return pack2(rcpf(a), rcpf(b));
}

#define ABSM 0x7FFFFFFF7FFFFFFFULL
#define NEGM 0x8000000080000000ULL

__global__ __launch_bounds__(NTHREADS, 8)
void robust_sum_kernel(const float* __restrict__ x,
                       const float* __restrict__ w,
                       float* __restrict__ out)
{
    __shared__ ulonglong2 xsd[DIN];        // 16 KB: {(xb0,xb0),(xb1,xb1)} per i
    __shared__ ull red[4][32][4];          // 4 KB: [iq][lane]{q_b0,q_b1,w_b0,w_b1}

    const int tid  = threadIdx.x;
    const int iq   = tid >> 5;             // warp == i-chunk 0..3 (256 i each)
    const int lane = tid & 31;
    const int o0   = blockIdx.x * 64 + lane * 2;
    const int b0   = blockIdx.y * 2;

    // Stage x pre-duplicated: one-time cost, saves 4 movs per inner 2i-step.
    for (int t = tid; t < DIN; t += NTHREADS) {
        float x0 = x[(size_t)b0 * DIN + t];
        float x1 = x[(size_t)(b0 + 1) * DIN + t];
        xsd[t] = make_ulonglong2(pack2(x0, x0), pack2(x1, x1));
    }
    __syncthreads();

    const ulonglong2* xq    = &xsd[iq * ICHUNK];
    const float*      wbase = w + (size_t)(iq * ICHUNK) * DOUT + o0;

    // ---- pass 0: z = x @ W (as c = z/DIN), packed over (o0,o1) ----
    ull s0 = 0ULL, s1 = 0ULL;              // per-b accumulators
    #pragma unroll 4
    for (int i = 0; i < ICHUNK; i++) {
        ull wv = __ldg((const ull*)(wbase + (size_t)i * DOUT));
        ulonglong2 xv = xq[i];             // LDS.128: both dup-packed x's
        s0 = fma2(xv.x, wv, s0);
        s1 = fma2(xv.y, wv, s1);
    }
    red[iq][lane][0] = s0;
    red[iq][lane][1] = s1;
    __syncthreads();
    ull c0p, c1p;                          // packed c per b: (c_o0, c_o1)
    {
        ull a0 = 0ULL, a1 = 0ULL;
        #pragma unroll
        for (int j = 0; j < 4; j++) {
            a0 = add2(a0, red[j][lane][0]);
            a1 = add2(a1, red[j][lane][1]);
        }
        const ull inv = pack2(1.0f / DIN, 1.0f / DIN);
        c0p = mul2(a0, inv);
        c1p = mul2(a1, inv);
    }

    const ull EPS2 = pack2(EPSILON, EPSILON);

    // ---- K IRLS iterations: paired i (1 rcp2 per 2i per b) ----
    #pragma unroll 1
    for (int k = 0; k < KITER; k++) {
        const ull nc0 = c0p ^ NEGM;
        const ull nc1 = c1p ^ NEGM;
        ull q0 = 0ULL, q1 = 0ULL, w0 = 0ULL, w1 = 0ULL;
        #pragma unroll 4
        for (int i = 0; i < ICHUNK; i += 2) {
            ull wva = __ldg((const ull*)(wbase + (size_t)i * DOUT));
            ull wvb = __ldg((const ull*)(wbase + (size_t)(i + 1) * DOUT));
            ulonglong2 xa = xq[i];         // {(x0,x0),(x1,x1)} at i
            ulonglong2 xb = xq[i + 1];     // ... at i+1
            {   // b0
                ull ta = fma2(xa.x, wva, nc0);
                ull tb = fma2(xb.x, wvb, nc0);
                ull da = add2(ta & ABSM, EPS2);
                ull db = add2(tb & ABSM, EPS2);
                ull r  = rcp2(mul2(da, db));
                ull cr = fma2(ta, db, mul2(tb, da));
                q0 = fma2(cr, r, q0);
                w0 = fma2(add2(da, db), r, w0);
            }
            {   // b1
                ull ta = fma2(xa.y, wva, nc1);
                ull tb = fma2(xb.y, wvb, nc1);
                ull da = add2(ta & ABSM, EPS2);
                ull db = add2(tb & ABSM, EPS2);
                ull r  = rcp2(mul2(da, db));
                ull cr = fma2(ta, db, mul2(tb, da));
                q1 = fma2(cr, r, q1);
                w1 = fma2(add2(da, db), r, w1);
            }
        }
        __syncthreads();               // previous reduce reads done
        {
            ull* rp = red[iq][lane];
            rp[0] = q0; rp[1] = q1; rp[2] = w0; rp[3] = w1;
        }
        __syncthreads();
        ull qa = 0ULL, qb = 0ULL, wa = 0ULL, wb = 0ULL;
        #pragma unroll
        for (int j = 0; j < 4; j++) {
            const ull* rp = red[j][lane];
            qa = add2(qa, rp[0]);
            qb = add2(qb, rp[1]);
            wa = add2(wa, rp[2]);
            wb = add2(wb, rp[3]);
        }
        float qlo, qhi, wlo, whi, clo, chi;
        unpack2(c0p, clo, chi); unpack2(qa, qlo, qhi); unpack2(wa, wlo, whi);
        c0p = pack2(__fdividef(fmaf(clo, wlo, qlo), fmaxf(wlo, 1e-12f)),
                    __fdividef(fmaf(chi, whi, qhi), fmaxf(whi, 1e-12f)));
        unpack2(c1p, clo, chi); unpack2(qb, qlo, qhi); unpack2(wb, wlo, whi);
        c1p = pack2(__fdividef(fmaf(clo, wlo, qlo), fmaxf(wlo, 1e-12f)),
                    __fdividef(fmaf(chi, whi, qhi), fmaxf(whi, 1e-12f)));
    }

    if (iq == 0) {
        const float D = (float)DIN;
        float lo, hi;
        unpack2(c0p, lo, hi);
        *(float2*)(out + (size_t)(b0 + 0) * DOUT + o0) = make_float2(D * lo, D * hi);
        unpack2(c1p, lo, hi);
        *(float2*)(out + (size_t)(b0 + 1) * DOUT + o0) = make_float2(D * lo, D * hi);
    }
}

extern "C" void kernel_launch(void* const* d_in, const int* in_sizes, int n_in,
                              void* d_out, int out_size)
{
    const float* x = (const float*)d_in[0];   // (128, 1024)
    const float* w = (const float*)d_in[1];   // (1024, 1024)
    float* out = (float*)d_out;               // (128, 1024)

    dim3 grid(DOUT / 64, 128 / 2);            // (16, 64) = 1024 blocks
    robust_sum_kernel<<<grid, NTHREADS>>>(x, w, out);
}

// round 14
// speedup vs baseline: 1.0139x; 1.0139x over previous
#include <cuda_runtime.h>
#include <cuda_bf16.h>

// RobustSum L1 IRLS (K=3): x(128,1024) @ W(1024,1024) -> z(128,1024), fp32.
//
// Per (b,o): c = z/D1; t_i = x_i*W_io - c; r_i = 1/(|t_i|+eps);
// q = sum r_i t_i, sw = sum r_i; c' = (q + c*sw)/max(sw,1e-12); out = D1*c.
// Pairing (exact): with d = |t|+eps,
//   r_i + r_j       = (d_i+d_j) * rcp(d_i*d_j)
//   r_i t_i+r_j t_j = (t_i d_j + t_j d_i) * rcp(d_i*d_j)
//
// R14 = R12 (best, 145.4us) + (a) explicit 1-group weight-load lookahead in
// the IRLS loop (load-to-use distance ~2 unrolled groups > L2 latency; the
// 64KB/CTA weight tile can't stay L1-resident at 7 CTAs/SM, so loads are
// L2-latency bound), + (b) pass-0 unroll 8 (cheap MLP).
// Shape unchanged: thread = 2b x 2o paired-i; block = 128 thr = 4 warps
// (warp = 256-i chunk); block = 2b x 64o; grid (16,64) = 1024 blocks.

#define DIN     1024
#define DOUT    1024
#define KITER   3
#define EPSILON 0.001f
#define ICHUNK  256
#define NTHREADS 128

typedef unsigned long long ull;

__device__ __forceinline__ ull pack2(float lo, float hi) {
    ull r; asm("mov.b64 %0, {%1,%2};" : "=l"(r) : "f"(lo), "f"(hi)); return r;
}
__device__ __forceinline__ void unpack2(ull v, float& lo, float& hi) {
    asm("mov.b64 {%0,%1}, %2;" : "=f"(lo), "=f"(hi) : "l"(v));
}
__device__ __forceinline__ ull fma2(ull a, ull b, ull c) {
    ull r; asm("fma.rn.f32x2 %0, %1, %2, %3;" : "=l"(r) : "l"(a), "l"(b), "l"(c)); return r;
}
__device__ __forceinline__ ull add2(ull a, ull b) {
    ull r; asm("add.rn.f32x2 %0, %1, %2;" : "=l"(r) : "l"(a), "l"(b)); return r;
}
__device__ __forceinline__ ull mul2(ull a, ull b) {
    ull r; asm("mul.rn.f32x2 %0, %1, %2;" : "=l"(r) : "l"(a), "l"(b)); return r;
}
__device__ __forceinline__ float rcpf(float a) {
    float r; asm("rcp.approx.f32 %0, %1;" : "=f"(r) : "f"(a)); return r;
}
__device__ __forceinline__ ull rcp2(ull m) {
    float a, b; unpack2(m, a, b);
    return pack2(rcpf(a), rcpf(b));
}

#define ABSM 0x7FFFFFFF7FFFFFFFULL
#define NEGM 0x8000000080000000ULL

__global__ __launch_bounds__(NTHREADS, 8)
void robust_sum_kernel(const float* __restrict__ x,
                       const float* __restrict__ w,
                       float* __restrict__ out)
{
    __shared__ float2 xs2[DIN];            // 8 KB: {x[b0][i], x[b1][i]}
    __shared__ ull red[4][32][4];          // 4 KB: [iq][lane]{q_b0,q_b1,w_b0,w_b1}

    const int tid  = threadIdx.x;
    const int iq   = tid >> 5;             // warp == i-chunk 0..3 (256 i each)
    const int lane = tid & 31;
    const int o0   = blockIdx.x * 64 + lane * 2;
    const int b0   = blockIdx.y * 2;

    // Stage x interleaved pairs (coalesced row reads).
    for (int t = tid; t < DIN; t += NTHREADS) {
        xs2[t] = make_float2(x[(size_t)b0 * DIN + t],
                             x[(size_t)(b0 + 1) * DIN + t]);
    }
    __syncthreads();

    const float2* xp    = &xs2[iq * ICHUNK];
    const float*  wbase = w + (size_t)(iq * ICHUNK) * DOUT + o0;

    // ---- pass 0: z = x @ W (as c = z/DIN), packed over (o0,o1) ----
    ull s0 = 0ULL, s1 = 0ULL;              // per-b accumulators
    #pragma unroll 8
    for (int i = 0; i < ICHUNK; i++) {
        ull wv = __ldg((const ull*)(wbase + (size_t)i * DOUT));
        float2 xv = xp[i];
        s0 = fma2(pack2(xv.x, xv.x), wv, s0);
        s1 = fma2(pack2(xv.y, xv.y), wv, s1);
    }
    red[iq][lane][0] = s0;
    red[iq][lane][1] = s1;
    __syncthreads();
    ull c0p, c1p;                          // packed c per b: (c_o0, c_o1)
    {
        ull a0 = 0ULL, a1 = 0ULL;
        #pragma unroll
        for (int j = 0; j < 4; j++) {
            a0 = add2(a0, red[j][lane][0]);
            a1 = add2(a1, red[j][lane][1]);
        }
        const ull inv = pack2(1.0f / DIN, 1.0f / DIN);
        c0p = mul2(a0, inv);
        c1p = mul2(a1, inv);
    }

    const ull EPS2 = pack2(EPSILON, EPSILON);

    // ---- K IRLS iterations: paired i (1 rcp2 per 2i per b) ----
    #pragma unroll 1
    for (int k = 0; k < KITER; k++) {
        const ull nc0 = c0p ^ NEGM;
        const ull nc1 = c1p ^ NEGM;
        ull q0 = 0ULL, q1 = 0ULL, w0 = 0ULL, w1 = 0ULL;
        // 1-group lookahead: weights for step i land ~2 groups before use.
        ull wva = __ldg((const ull*)(wbase));
        ull wvb = __ldg((const ull*)(wbase + DOUT));
        #pragma unroll 4
        for (int i = 0; i < ICHUNK; i += 2) {
            const int ip = min(i + 2, ICHUNK - 2);
            ull nva = __ldg((const ull*)(wbase + (size_t)ip * DOUT));
            ull nvb = __ldg((const ull*)(wbase + (size_t)(ip + 1) * DOUT));
            float4 xv = *(const float4*)(xp + i);   // {x0[i],x1[i],x0[i+1],x1[i+1]}
            {   // b0: i uses xv.x, i+1 uses xv.z
                ull ta = fma2(pack2(xv.x, xv.x), wva, nc0);
                ull tb = fma2(pack2(xv.z, xv.z), wvb, nc0);
                ull da = add2(ta & ABSM, EPS2);
                ull db = add2(tb & ABSM, EPS2);
                ull r  = rcp2(mul2(da, db));
                ull cr = fma2(ta, db, mul2(tb, da));
                q0 = fma2(cr, r, q0);
                w0 = fma2(add2(da, db), r, w0);
            }
            {   // b1: i uses xv.y, i+1 uses xv.w
                ull ta = fma2(pack2(xv.y, xv.y), wva, nc1);
                ull tb = fma2(pack2(xv.w, xv.w), wvb, nc1);
                ull da = add2(ta & ABSM, EPS2);
                ull db = add2(tb & ABSM, EPS2);
                ull r  = rcp2(mul2(da, db));
                ull cr = fma2(ta, db, mul2(tb, da));
                q1 = fma2(cr, r, q1);
                w1 = fma2(add2(da, db), r, w1);
            }
            wva = nva;
            wvb = nvb;
        }
        __syncthreads();               // previous reduce reads done
        {
            ull* rp = red[iq][lane];
            rp[0] = q0; rp[1] = q1; rp[2] = w0; rp[3] = w1;
        }
        __syncthreads();
        ull qa = 0ULL, qb = 0ULL, wa = 0ULL, wb = 0ULL;
        #pragma unroll
        for (int j = 0; j < 4; j++) {
            const ull* rp = red[j][lane];
            qa = add2(qa, rp[0]);
            qb = add2(qb, rp[1]);
            wa = add2(wa, rp[2]);
            wb = add2(wb, rp[3]);
        }
        float qlo, qhi, wlo, whi, clo, chi;
        unpack2(c0p, clo, chi); unpack2(qa, qlo, qhi); unpack2(wa, wlo, whi);
        c0p = pack2(__fdividef(fmaf(clo, wlo, qlo), fmaxf(wlo, 1e-12f)),
                    __fdividef(fmaf(chi, whi, qhi), fmaxf(whi, 1e-12f)));
        unpack2(c1p, clo, chi); unpack2(qb, qlo, qhi); unpack2(wb, wlo, whi);
        c1p = pack2(__fdividef(fmaf(clo, wlo, qlo), fmaxf(wlo, 1e-12f)),
                    __fdividef(fmaf(chi, whi, qhi), fmaxf(whi, 1e-12f)));
    }

    if (iq == 0) {
        const float D = (float)DIN;
        float lo, hi;
        unpack2(c0p, lo, hi);
        *(float2*)(out + (size_t)(b0 + 0) * DOUT + o0) = make_float2(D * lo, D * hi);
        unpack2(c1p, lo, hi);
        *(float2*)(out + (size_t)(b0 + 1) * DOUT + o0) = make_float2(D * lo, D * hi);
    }
}

extern "C" void kernel_launch(void* const* d_in, const int* in_sizes, int n_in,
                              void* d_out, int out_size)
{
    const float* x = (const float*)d_in[0];   // (128, 1024)
    const float* w = (const float*)d_in[1];   // (1024, 1024)
    float* out = (float*)d_out;               // (128, 1024)

    dim3 grid(DOUT / 64, 128 / 2);            // (16, 64) = 1024 blocks
    robust_sum_kernel<<<grid, NTHREADS>>>(x, w, out);
}

// round 15
// speedup vs baseline: 1.0425x; 1.0282x over previous
#include <cuda_runtime.h>
#include <cuda_bf16.h>

// RobustSum L1 IRLS (K=3): x(128,1024) @ W(1024,1024) -> z(128,1024), fp32.
//
// Per (b,o): c = z/D1; t_i = x_i*W_io - c; r_i = 1/(|t_i|+eps);
// q = sum r_i t_i, sw = sum r_i; c' = (q + c*sw)/max(sw,1e-12); out = D1*c.
// Pairing (exact): with d = |t|+eps,
//   r_i + r_j       = (d_i+d_j) * rcp(d_i*d_j)
//   r_i t_i+r_j t_j = (t_i d_j + t_j d_i) * rcp(d_i*d_j)
//
// R15 = R14's load lookahead (issue 56.6->62.5% verified) with its alu cost
// stripped: no min() (peeled last group), pointer-walk addressing with
// immediate offsets (1 IADD/step instead of per-load IMAD + IMNMX).
// Shape = R12 (best): thread = 2b x 2o paired-i; block = 128 thr = 4 warps
// (warp = 256-i chunk); block = 2b x 64o; grid (16,64) = 1024 blocks.

#define DIN     1024
#define DOUT    1024
#define KITER   3
#define EPSILON 0.001f
#define ICHUNK  256
#define NTHREADS 128

typedef unsigned long long ull;

__device__ __forceinline__ ull pack2(float lo, float hi) {
    ull r; asm("mov.b64 %0, {%1,%2};" : "=l"(r) : "f"(lo), "f"(hi)); return r;
}
__device__ __forceinline__ void unpack2(ull v, float& lo, float& hi) {
    asm("mov.b64 {%0,%1}, %2;" : "=f"(lo), "=f"(hi) : "l"(v));
}
__device__ __forceinline__ ull fma2(ull a, ull b, ull c) {
    ull r; asm("fma.rn.f32x2 %0, %1, %2, %3;" : "=l"(r) : "l"(a), "l"(b), "l"(c)); return r;
}
__device__ __forceinline__ ull add2(ull a, ull b) {
    ull r; asm("add.rn.f32x2 %0, %1, %2;" : "=l"(r) : "l"(a), "l"(b)); return r;
}
__device__ __forceinline__ ull mul2(ull a, ull b) {
    ull r; asm("mul.rn.f32x2 %0, %1, %2;" : "=l"(r) : "l"(a), "l"(b)); return r;
}
__device__ __forceinline__ float rcpf(float a) {
    float r; asm("rcp.approx.f32 %0, %1;" : "=f"(r) : "f"(a)); return r;
}
__device__ __forceinline__ ull rcp2(ull m) {
    float a, b; unpack2(m, a, b);
    return pack2(rcpf(a), rcpf(b));
}

#define ABSM 0x7FFFFFFF7FFFFFFFULL
#define NEGM 0x8000000080000000ULL

// One paired step for both b's; w-operands already loaded.
#define IRLS_STEP(XV, WVA, WVB)                                              \
    do {                                                                     \
        {   /* b0: i uses XV.x, i+1 uses XV.z */                             \
            ull ta = fma2(pack2(XV.x, XV.x), (WVA), nc0);                    \
            ull tb = fma2(pack2(XV.z, XV.z), (WVB), nc0);                    \
            ull da = add2(ta & ABSM, EPS2);                                  \
            ull db = add2(tb & ABSM, EPS2);                                  \
            ull r  = rcp2(mul2(da, db));                                     \
            ull cr = fma2(ta, db, mul2(tb, da));                             \
            q0 = fma2(cr, r, q0);                                            \
            w0 = fma2(add2(da, db), r, w0);                                  \
        }                                                                    \
        {   /* b1: i uses XV.y, i+1 uses XV.w */                             \
            ull ta = fma2(pack2(XV.y, XV.y), (WVA), nc1);                    \
            ull tb = fma2(pack2(XV.w, XV.w), (WVB), nc1);                    \
            ull da = add2(ta & ABSM, EPS2);                                  \
            ull db = add2(tb & ABSM, EPS2);                                  \
            ull r  = rcp2(mul2(da, db));                                     \
            ull cr = fma2(ta, db, mul2(tb, da));                             \
            q1 = fma2(cr, r, q1);                                            \
            w1 = fma2(add2(da, db), r, w1);                                  \
        }                                                                    \
    } while (0)

__global__ __launch_bounds__(NTHREADS, 8)
void robust_sum_kernel(const float* __restrict__ x,
                       const float* __restrict__ w,
                       float* __restrict__ out)
{
    __shared__ float2 xs2[DIN];            // 8 KB: {x[b0][i], x[b1][i]}
    __shared__ ull red[4][32][4];          // 4 KB: [iq][lane]{q_b0,q_b1,w_b0,w_b1}

    const int tid  = threadIdx.x;
    const int iq   = tid >> 5;             // warp == i-chunk 0..3 (256 i each)
    const int lane = tid & 31;
    const int o0   = blockIdx.x * 64 + lane * 2;
    const int b0   = blockIdx.y * 2;

    for (int t = tid; t < DIN; t += NTHREADS) {
        xs2[t] = make_float2(x[(size_t)b0 * DIN + t],
                             x[(size_t)(b0 + 1) * DIN + t]);
    }
    __syncthreads();

    const float2* xp    = &xs2[iq * ICHUNK];
    const float*  wbase = w + (size_t)(iq * ICHUNK) * DOUT + o0;

    // ---- pass 0: z = x @ W (as c = z/DIN), packed over (o0,o1) ----
    ull s0 = 0ULL, s1 = 0ULL;
    #pragma unroll 8
    for (int i = 0; i < ICHUNK; i++) {
        ull wv = __ldg((const ull*)(wbase + (size_t)i * DOUT));
        float2 xv = xp[i];
        s0 = fma2(pack2(xv.x, xv.x), wv, s0);
        s1 = fma2(pack2(xv.y, xv.y), wv, s1);
    }
    red[iq][lane][0] = s0;
    red[iq][lane][1] = s1;
    __syncthreads();
    ull c0p, c1p;
    {
        ull a0 = 0ULL, a1 = 0ULL;
        #pragma unroll
        for (int j = 0; j < 4; j++) {
            a0 = add2(a0, red[j][lane][0]);
            a1 = add2(a1, red[j][lane][1]);
        }
        const ull inv = pack2(1.0f / DIN, 1.0f / DIN);
        c0p = mul2(a0, inv);
        c1p = mul2(a1, inv);
    }

    const ull EPS2 = pack2(EPSILON, EPSILON);

    // ---- K IRLS iterations: paired i, 1-group lookahead, no min() ----
    #pragma unroll 1
    for (int k = 0; k < KITER; k++) {
        const ull nc0 = c0p ^ NEGM;
        const ull nc1 = c1p ^ NEGM;
        ull q0 = 0ULL, q1 = 0ULL, w0 = 0ULL, w1 = 0ULL;

        const ull* wp = (const ull*)wbase;          // row stride DOUT/2 ull
        ull wva = __ldg(wp);
        ull wvb = __ldg(wp + DOUT / 2);
        // steady state: prefetch i+2/i+3 with immediate offsets, walk pointer
        #pragma unroll 4
        for (int i = 0; i < ICHUNK - 2; i += 2) {
            ull nva = __ldg(wp + 2 * (DOUT / 2));
            ull nvb = __ldg(wp + 3 * (DOUT / 2));
            float4 xv = *(const float4*)(xp + i);
            IRLS_STEP(xv, wva, wvb);
            wva = nva;
            wvb = nvb;
            wp += 2 * (DOUT / 2);
        }
        {   // peeled last group (i = ICHUNK-2): no prefetch needed
            float4 xv = *(const float4*)(xp + (ICHUNK - 2));
            IRLS_STEP(xv, wva, wvb);
        }

        __syncthreads();
        {
            ull* rp = red[iq][lane];
            rp[0] = q0; rp[1] = q1; rp[2] = w0; rp[3] = w1;
        }
        __syncthreads();
        ull qa = 0ULL, qb = 0ULL, wa = 0ULL, wb = 0ULL;
        #pragma unroll
        for (int j = 0; j < 4; j++) {
            const ull* rp = red[j][lane];
            qa = add2(qa, rp[0]);
            qb = add2(qb, rp[1]);
            wa = add2(wa, rp[2]);
            wb = add2(wb, rp[3]);
        }
        float qlo, qhi, wlo, whi, clo, chi;
        unpack2(c0p, clo, chi); unpack2(qa, qlo, qhi); unpack2(wa, wlo, whi);
        c0p = pack2(__fdividef(fmaf(clo, wlo, qlo), fmaxf(wlo, 1e-12f)),
                    __fdividef(fmaf(chi, whi, qhi), fmaxf(whi, 1e-12f)));
        unpack2(c1p, clo, chi); unpack2(qb, qlo, qhi); unpack2(wb, wlo, whi);
        c1p = pack2(__fdividef(fmaf(clo, wlo, qlo), fmaxf(wlo, 1e-12f)),
                    __fdividef(fmaf(chi, whi, qhi), fmaxf(whi, 1e-12f)));
    }

    if (iq == 0) {
        const float D = (float)DIN;
        float lo, hi;
        unpack2(c0p, lo, hi);
        *(float2*)(out + (size_t)(b0 + 0) * DOUT + o0) = make_float2(D * lo, D * hi);
        unpack2(c1p, lo, hi);
        *(float2*)(out + (size_t)(b0 + 1) * DOUT + o0) = make_float2(D * lo, D * hi);
    }
}

extern "C" void kernel_launch(void* const* d_in, const int* in_sizes, int n_in,
                              void* d_out, int out_size)
{
    const float* x = (const float*)d_in[0];   // (128, 1024)
    const float* w = (const float*)d_in[1];   // (1024, 1024)
    float* out = (float*)d_out;               // (128, 1024)

    dim3 grid(DOUT / 64, 128 / 2);            // (16, 64) = 1024 blocks
    robust_sum_kernel<<<grid, NTHREADS>>>(x, w, out);
}

// round 16
// speedup vs baseline: 1.0655x; 1.0220x over previous
#include <cuda_runtime.h>
#include <cuda_bf16.h>

// RobustSum L1 IRLS (K=3): x(128,1024) @ W(1024,1024) -> z(128,1024), fp32.
//
// Per (b,o): c = z/D1; t_i = x_i*W_io - c; r_i = 1/(|t_i|+eps);
// q = sum r_i t_i, sw = sum r_i; c' = (q + c*sw)/max(sw,1e-12); out = D1*c.
// Pairing (exact): with d = |t|+eps,
//   r_i + r_j       = (d_i+d_j) * rcp(d_i*d_j)
//   r_i t_i+r_j t_j = (t_i d_j + t_j d_i) * rcp(d_i*d_j)
//
// R16 = R15 (tied-best, 145.4us) + IRLS unroll 8 (loop overhead amortized,
// deeper LDG batching window). All else identical: thread = 2b x 2o paired-i,
// 1-group load lookahead, pointer-walk addressing; block = 128 thr = 4 warps
// (warp = 256-i chunk); block = 2b x 64o; grid (16,64) = 1024 blocks.

#define DIN     1024
#define DOUT    1024
#define KITER   3
#define EPSILON 0.001f
#define ICHUNK  256
#define NTHREADS 128

typedef unsigned long long ull;

__device__ __forceinline__ ull pack2(float lo, float hi) {
    ull r; asm("mov.b64 %0, {%1,%2};" : "=l"(r) : "f"(lo), "f"(hi)); return r;
}
__device__ __forceinline__ void unpack2(ull v, float& lo, float& hi) {
    asm("mov.b64 {%0,%1}, %2;" : "=f"(lo), "=f"(hi) : "l"(v));
}
__device__ __forceinline__ ull fma2(ull a, ull b, ull c) {
    ull r; asm("fma.rn.f32x2 %0, %1, %2, %3;" : "=l"(r) : "l"(a), "l"(b), "l"(c)); return r;
}
__device__ __forceinline__ ull add2(ull a, ull b) {
    ull r; asm("add.rn.f32x2 %0, %1, %2;" : "=l"(r) : "l"(a), "l"(b)); return r;
}
__device__ __forceinline__ ull mul2(ull a, ull b) {
    ull r; asm("mul.rn.f32x2 %0, %1, %2;" : "=l"(r) : "l"(a), "l"(b)); return r;
}
__device__ __forceinline__ float rcpf(float a) {
    float r; asm("rcp.approx.f32 %0, %1;" : "=f"(r) : "f"(a)); return r;
}
__device__ __forceinline__ ull rcp2(ull m) {
    float a, b; unpack2(m, a, b);
    return pack2(rcpf(a), rcpf(b));
}

#define ABSM 0x7FFFFFFF7FFFFFFFULL
#define NEGM 0x8000000080000000ULL

// One paired step for both b's; w-operands already loaded.
#define IRLS_STEP(XV, WVA, WVB)                                              \
    do {                                                                     \
        {   /* b0: i uses XV.x, i+1 uses XV.z */                             \
            ull ta = fma2(pack2(XV.x, XV.x), (WVA), nc0);                    \
            ull tb = fma2(pack2(XV.z, XV.z), (WVB), nc0);                    \
            ull da = add2(ta & ABSM, EPS2);                                  \
            ull db = add2(tb & ABSM, EPS2);                                  \
            ull r  = rcp2(mul2(da, db));                                     \
            ull cr = fma2(ta, db, mul2(tb, da));                             \
            q0 = fma2(cr, r, q0);                                            \
            w0 = fma2(add2(da, db), r, w0);                                  \
        }                                                                    \
        {   /* b1: i uses XV.y, i+1 uses XV.w */                             \
            ull ta = fma2(pack2(XV.y, XV.y), (WVA), nc1);                    \
            ull tb = fma2(pack2(XV.w, XV.w), (WVB), nc1);                    \
            ull da = add2(ta & ABSM, EPS2);                                  \
            ull db = add2(tb & ABSM, EPS2);                                  \
            ull r  = rcp2(mul2(da, db));                                     \
            ull cr = fma2(ta, db, mul2(tb, da));                             \
            q1 = fma2(cr, r, q1);                                            \
            w1 = fma2(add2(da, db), r, w1);                                  \
        }                                                                    \
    } while (0)

__global__ __launch_bounds__(NTHREADS, 8)
void robust_sum_kernel(const float* __restrict__ x,
                       const float* __restrict__ w,
                       float* __restrict__ out)
{
    __shared__ float2 xs2[DIN];            // 8 KB: {x[b0][i], x[b1][i]}
    __shared__ ull red[4][32][4];          // 4 KB: [iq][lane]{q_b0,q_b1,w_b0,w_b1}

    const int tid  = threadIdx.x;
    const int iq   = tid >> 5;             // warp == i-chunk 0..3 (256 i each)
    const int lane = tid & 31;
    const int o0   = blockIdx.x * 64 + lane * 2;
    const int b0   = blockIdx.y * 2;

    for (int t = tid; t < DIN; t += NTHREADS) {
        xs2[t] = make_float2(x[(size_t)b0 * DIN + t],
                             x[(size_t)(b0 + 1) * DIN + t]);
    }
    __syncthreads();

    const float2* xp    = &xs2[iq * ICHUNK];
    const float*  wbase = w + (size_t)(iq * ICHUNK) * DOUT + o0;

    // ---- pass 0: z = x @ W (as c = z/DIN), packed over (o0,o1) ----
    ull s0 = 0ULL, s1 = 0ULL;
    #pragma unroll 8
    for (int i = 0; i < ICHUNK; i++) {
        ull wv = __ldg((const ull*)(wbase + (size_t)i * DOUT));
        float2 xv = xp[i];
        s0 = fma2(pack2(xv.x, xv.x), wv, s0);
        s1 = fma2(pack2(xv.y, xv.y), wv, s1);
    }
    red[iq][lane][0] = s0;
    red[iq][lane][1] = s1;
    __syncthreads();
    ull c0p, c1p;
    {
        ull a0 = 0ULL, a1 = 0ULL;
        #pragma unroll
        for (int j = 0; j < 4; j++) {
            a0 = add2(a0, red[j][lane][0]);
            a1 = add2(a1, red[j][lane][1]);
        }
        const ull inv = pack2(1.0f / DIN, 1.0f / DIN);
        c0p = mul2(a0, inv);
        c1p = mul2(a1, inv);
    }

    const ull EPS2 = pack2(EPSILON, EPSILON);

    // ---- K IRLS iterations: paired i, 1-group lookahead, unroll 8 ----
    #pragma unroll 1
    for (int k = 0; k < KITER; k++) {
        const ull nc0 = c0p ^ NEGM;
        const ull nc1 = c1p ^ NEGM;
        ull q0 = 0ULL, q1 = 0ULL, w0 = 0ULL, w1 = 0ULL;

        const ull* wp = (const ull*)wbase;          // row stride DOUT/2 ull
        ull wva = __ldg(wp);
        ull wvb = __ldg(wp + DOUT / 2);
        #pragma unroll 8
        for (int i = 0; i < ICHUNK - 2; i += 2) {
            ull nva = __ldg(wp + 2 * (DOUT / 2));
            ull nvb = __ldg(wp + 3 * (DOUT / 2));
            float4 xv = *(const float4*)(xp + i);
            IRLS_STEP(xv, wva, wvb);
            wva = nva;
            wvb = nvb;
            wp += 2 * (DOUT / 2);
        }
        {   // peeled last group (i = ICHUNK-2): no prefetch needed
            float4 xv = *(const float4*)(xp + (ICHUNK - 2));
            IRLS_STEP(xv, wva, wvb);
        }

        __syncthreads();
        {
            ull* rp = red[iq][lane];
            rp[0] = q0; rp[1] = q1; rp[2] = w0; rp[3] = w1;
        }
        __syncthreads();
        ull qa = 0ULL, qb = 0ULL, wa = 0ULL, wb = 0ULL;
        #pragma unroll
        for (int j = 0; j < 4; j++) {
            const ull* rp = red[j][lane];
            qa = add2(qa, rp[0]);
            qb = add2(qb, rp[1]);
            wa = add2(wa, rp[2]);
            wb = add2(wb, rp[3]);
        }
        float qlo, qhi, wlo, whi, clo, chi;
        unpack2(c0p, clo, chi); unpack2(qa, qlo, qhi); unpack2(wa, wlo, whi);
        c0p = pack2(__fdividef(fmaf(clo, wlo, qlo), fmaxf(wlo, 1e-12f)),
                    __fdividef(fmaf(chi, whi, qhi), fmaxf(whi, 1e-12f)));
        unpack2(c1p, clo, chi); unpack2(qb, qlo, qhi); unpack2(wb, wlo, whi);
        c1p = pack2(__fdividef(fmaf(clo, wlo, qlo), fmaxf(wlo, 1e-12f)),
                    __fdividef(fmaf(chi, whi, qhi), fmaxf(whi, 1e-12f)));
    }

    if (iq == 0) {
        const float D = (float)DIN;
        float lo, hi;
        unpack2(c0p, lo, hi);
        *(float2*)(out + (size_t)(b0 + 0) * DOUT + o0) = make_float2(D * lo, D * hi);
        unpack2(c1p, lo, hi);
        *(float2*)(out + (size_t)(b0 + 1) * DOUT + o0) = make_float2(D * lo, D * hi);
    }
}

extern "C" void kernel_launch(void* const* d_in, const int* in_sizes, int n_in,
                              void* d_out, int out_size)
{
    const float* x = (const float*)d_in[0];   // (128, 1024)
    const float* w = (const float*)d_in[1];   // (1024, 1024)
    float* out = (float*)d_out;               // (128, 1024)

    dim3 grid(DOUT / 64, 128 / 2);            // (16, 64) = 1024 blocks
    robust_sum_kernel<<<grid, NTHREADS>>>(x, w, out);
}

// round 17
// speedup vs baseline: 1.0727x; 1.0068x over previous
#include <cuda_runtime.h>
#include <cuda_bf16.h>

// RobustSum L1 IRLS (K=3): x(128,1024) @ W(1024,1024) -> z(128,1024), fp32.
//
// Per (b,o): c = z/D1; t_i = x_i*W_io - c; r_i = 1/(|t_i|+eps);
// q = sum r_i t_i, sw = sum r_i; c' = (q + c*sw)/max(sw,1e-12); out = D1*c.
// Pairing (exact): with d = |t|+eps,
//   r_i + r_j       = (d_i+d_j) * rcp(d_i*d_j)
//   r_i t_i+r_j t_j = (t_i d_j + t_j d_i) * rcp(d_i*d_j)
//
// R17 = R16 (best, 142.3us) minus the manual load-lookahead: with unroll 8,
// ptxas front-batches the 8 steps' LDGs itself (MLP ~8 > manual 2), so the
// explicit rotation (2 movs + IADD per step, ~4 regs) is pure duplicate cost.
// Shape: thread = 2b x 2o paired-i; block = 128 thr = 4 warps (warp = 256-i
// chunk); block = 2b x 64o; grid (16,64) = 1024 blocks; launch_bounds(128,8).

#define DIN     1024
#define DOUT    1024
#define KITER   3
#define EPSILON 0.001f
#define ICHUNK  256
#define NTHREADS 128

typedef unsigned long long ull;

__device__ __forceinline__ ull pack2(float lo, float hi) {
    ull r; asm("mov.b64 %0, {%1,%2};" : "=l"(r) : "f"(lo), "f"(hi)); return r;
}
__device__ __forceinline__ void unpack2(ull v, float& lo, float& hi) {
    asm("mov.b64 {%0,%1}, %2;" : "=f"(lo), "=f"(hi) : "l"(v));
}
__device__ __forceinline__ ull fma2(ull a, ull b, ull c) {
    ull r; asm("fma.rn.f32x2 %0, %1, %2, %3;" : "=l"(r) : "l"(a), "l"(b), "l"(c)); return r;
}
__device__ __forceinline__ ull add2(ull a, ull b) {
    ull r; asm("add.rn.f32x2 %0, %1, %2;" : "=l"(r) : "l"(a), "l"(b)); return r;
}
__device__ __forceinline__ ull mul2(ull a, ull b) {
    ull r; asm("mul.rn.f32x2 %0, %1, %2;" : "=l"(r) : "l"(a), "l"(b)); return r;
}
__device__ __forceinline__ float rcpf(float a) {
    float r; asm("rcp.approx.f32 %0, %1;" : "=f"(r) : "f"(a)); return r;
}
__device__ __forceinline__ ull rcp2(ull m) {
    float a, b; unpack2(m, a, b);
    return pack2(rcpf(a), rcpf(b));
}

#define ABSM 0x7FFFFFFF7FFFFFFFULL
#define NEGM 0x8000000080000000ULL

// One paired step for both b's; w-operands already loaded.
#define IRLS_STEP(XV, WVA, WVB)                                              \
    do {                                                                     \
        {   /* b0: i uses XV.x, i+1 uses XV.z */                             \
            ull ta = fma2(pack2(XV.x, XV.x), (WVA), nc0);                    \
            ull tb = fma2(pack2(XV.z, XV.z), (WVB), nc0);                    \
            ull da = add2(ta & ABSM, EPS2);                                  \
            ull db = add2(tb & ABSM, EPS2);                                  \
            ull r  = rcp2(mul2(da, db));                                     \
            ull cr = fma2(ta, db, mul2(tb, da));                             \
            q0 = fma2(cr, r, q0);                                            \
            w0 = fma2(add2(da, db), r, w0);                                  \
        }                                                                    \
        {   /* b1: i uses XV.y, i+1 uses XV.w */                             \
            ull ta = fma2(pack2(XV.y, XV.y), (WVA), nc1);                    \
            ull tb = fma2(pack2(XV.w, XV.w), (WVB), nc1);                    \
            ull da = add2(ta & ABSM, EPS2);                                  \
            ull db = add2(tb & ABSM, EPS2);                                  \
            ull r  = rcp2(mul2(da, db));                                     \
            ull cr = fma2(ta, db, mul2(tb, da));                             \
            q1 = fma2(cr, r, q1);                                            \
            w1 = fma2(add2(da, db), r, w1);                                  \
        }                                                                    \
    } while (0)

__global__ __launch_bounds__(NTHREADS, 8)
void robust_sum_kernel(const float* __restrict__ x,
                       const float* __restrict__ w,
                       float* __restrict__ out)
{
    __shared__ float2 xs2[DIN];            // 8 KB: {x[b0][i], x[b1][i]}
    __shared__ ull red[4][32][4];          // 4 KB: [iq][lane]{q_b0,q_b1,w_b0,w_b1}

    const int tid  = threadIdx.x;
    const int iq   = tid >> 5;             // warp == i-chunk 0..3 (256 i each)
    const int lane = tid & 31;
    const int o0   = blockIdx.x * 64 + lane * 2;
    const int b0   = blockIdx.y * 2;

    for (int t = tid; t < DIN; t += NTHREADS) {
        xs2[t] = make_float2(x[(size_t)b0 * DIN + t],
                             x[(size_t)(b0 + 1) * DIN + t]);
    }
    __syncthreads();

    const float2* xp    = &xs2[iq * ICHUNK];
    const float*  wbase = w + (size_t)(iq * ICHUNK) * DOUT + o0;

    // ---- pass 0: z = x @ W (as c = z/DIN), packed over (o0,o1) ----
    ull s0 = 0ULL, s1 = 0ULL;
    #pragma unroll 8
    for (int i = 0; i < ICHUNK; i++) {
        ull wv = __ldg((const ull*)(wbase + (size_t)i * DOUT));
        float2 xv = xp[i];
        s0 = fma2(pack2(xv.x, xv.x), wv, s0);
        s1 = fma2(pack2(xv.y, xv.y), wv, s1);
    }
    red[iq][lane][0] = s0;
    red[iq][lane][1] = s1;
    __syncthreads();
    ull c0p, c1p;
    {
        ull a0 = 0ULL, a1 = 0ULL;
        #pragma unroll
        for (int j = 0; j < 4; j++) {
            a0 = add2(a0, red[j][lane][0]);
            a1 = add2(a1, red[j][lane][1]);
        }
        const ull inv = pack2(1.0f / DIN, 1.0f / DIN);
        c0p = mul2(a0, inv);
        c1p = mul2(a1, inv);
    }

    const ull EPS2 = pack2(EPSILON, EPSILON);

    // ---- K IRLS iterations: paired i, unroll 8, compiler-batched loads ----
    #pragma unroll 1
    for (int k = 0; k < KITER; k++) {
        const ull nc0 = c0p ^ NEGM;
        const ull nc1 = c1p ^ NEGM;
        ull q0 = 0ULL, q1 = 0ULL, w0 = 0ULL, w1 = 0ULL;

        const ull* wp = (const ull*)wbase;          // row stride DOUT/2 ull
        #pragma unroll 8
        for (int i = 0; i < ICHUNK; i += 2) {
            ull wva = __ldg(wp);
            ull wvb = __ldg(wp + DOUT / 2);
            float4 xv = *(const float4*)(xp + i);
            IRLS_STEP(xv, wva, wvb);
            wp += DOUT;                             // advance 2 rows
        }

        __syncthreads();
        {
            ull* rp = red[iq][lane];
            rp[0] = q0; rp[1] = q1; rp[2] = w0; rp[3] = w1;
        }
        __syncthreads();
        ull qa = 0ULL, qb = 0ULL, wa = 0ULL, wb = 0ULL;
        #pragma unroll
        for (int j = 0; j < 4; j++) {
            const ull* rp = red[j][lane];
            qa = add2(qa, rp[0]);
            qb = add2(qb, rp[1]);
            wa = add2(wa, rp[2]);
            wb = add2(wb, rp[3]);
        }
        float qlo, qhi, wlo, whi, clo, chi;
        unpack2(c0p, clo, chi); unpack2(qa, qlo, qhi); unpack2(wa, wlo, whi);
        c0p = pack2(__fdividef(fmaf(clo, wlo, qlo), fmaxf(wlo, 1e-12f)),
                    __fdividef(fmaf(chi, whi, qhi), fmaxf(whi, 1e-12f)));
        unpack2(c1p, clo, chi); unpack2(qb, qlo, qhi); unpack2(wb, wlo, whi);
        c1p = pack2(__fdividef(fmaf(clo, wlo, qlo), fmaxf(wlo, 1e-12f)),
                    __fdividef(fmaf(chi, whi, qhi), fmaxf(whi, 1e-12f)));
    }

    if (iq == 0) {
        const float D = (float)DIN;
        float lo, hi;
        unpack2(c0p, lo, hi);
        *(float2*)(out + (size_t)(b0 + 0) * DOUT + o0) = make_float2(D * lo, D * hi);
        unpack2(c1p, lo, hi);
        *(float2*)(out + (size_t)(b0 + 1) * DOUT + o0) = make_float2(D * lo, D * hi);
    }
}

extern "C" void kernel_launch(void* const* d_in, const int* in_sizes, int n_in,
                              void* d_out, int out_size)
{
    const float* x = (const float*)d_in[0];   // (128, 1024)
    const float* w = (const float*)d_in[1];   // (1024, 1024)
    float* out = (float*)d_out;               // (128, 1024)

    dim3 grid(DOUT / 64, 128 / 2);            // (16, 64) = 1024 blocks
    robust_sum_kernel<<<grid, NTHREADS>>>(x, w, out);
}